// round 4
// baseline (speedup 1.0000x reference)
#include <cuda_runtime.h>
#include <math.h>

#define BATCH  8
#define NPTS   131072
#define DIM    32
#define NLAB   33
#define KINST  32
#define CHUNK  512
#define CHUNKS (NPTS / CHUNK)        // 256 per batch
#define THREADS 256
#define NWARP   8
#define WPTS    (CHUNK / NWARP)      // 64 points per warp
#define PAIRBLKS (2 * CHUNKS)        // 512 blocks per pair launch

// ---- scratch (no allocations allowed) ----
__device__ float g_sums[BATCH * NLAB * DIM];
__device__ float g_counts[BATCH * NLAB];
__device__ float g_hinge[BATCH * NLAB];

__global__ void k_zero() {
    int i = blockIdx.x * blockDim.x + threadIdx.x;
    if (i < BATCH * NLAB * DIM) g_sums[i] = 0.f;
    if (i < BATCH * NLAB) { g_counts[i] = 0.f; g_hinge[i] = 0.f; }
}

// Pass 1: per-(b,label) sums + counts for a 2-batch pair starting at b0.
// Warp-per-point lane-private SMEM RMW (race-free); loads staged 16-deep.
__global__ void __launch_bounds__(THREADS) k_pass1(const float* __restrict__ emb,
                                                   const int* __restrict__ lab,
                                                   int b0) {
    __shared__ float s_sums[NWARP][NLAB * DIM];
    __shared__ float s_cnt[NWARP][NLAB];
    int tid = threadIdx.x, wid = tid >> 5, lane = tid & 31;

    for (int i = tid; i < NWARP * NLAB * DIM; i += THREADS) (&s_sums[0][0])[i] = 0.f;
    for (int i = tid; i < NWARP * NLAB; i += THREADS)       (&s_cnt[0][0])[i]  = 0.f;
    __syncthreads();

    int b = b0 + blockIdx.x / CHUNKS;
    int chunk = blockIdx.x % CHUNKS;
    const float* ebase = emb + ((size_t)b * NPTS + (size_t)chunk * CHUNK) * DIM;
    const int*   lbase = lab + (size_t)b * NPTS + (size_t)chunk * CHUNK;

    float* ws = s_sums[wid];
    float* wc = s_cnt[wid];
    int p0 = wid * WPTS;

    for (int w = 0; w < WPTS; w += 32) {
        int myl = lbase[p0 + w + lane];                 // coalesced labels
        unsigned peers = __match_any_sync(0xffffffffu, myl);
        if ((__ffs(peers) - 1) == lane)                 // one leader per label
            wc[myl] += (float)__popc(peers);            // distinct addrs: no race
        #pragma unroll
        for (int h = 0; h < 32; h += 16) {
            float v[16];
            #pragma unroll
            for (int i = 0; i < 16; i++)                // 16 LDGs in flight
                v[i] = ebase[(size_t)(p0 + w + h + i) * DIM + lane];
            #pragma unroll
            for (int i = 0; i < 16; i++) {
                int l = __shfl_sync(0xffffffffu, myl, h + i);
                ws[l * DIM + lane] += v[i];             // lane-private: no race
            }
        }
    }
    __syncthreads();

    for (int i = tid; i < NLAB * DIM; i += THREADS) {
        float s = 0.f;
        #pragma unroll
        for (int w = 0; w < NWARP; w++) s += s_sums[w][i];
        atomicAdd(&g_sums[b * NLAB * DIM + i], s);
    }
    for (int i = tid; i < NLAB; i += THREADS) {
        float s = 0.f;
        #pragma unroll
        for (int w = 0; w < NWARP; w++) s += s_cnt[w][i];
        atomicAdd(&g_counts[b * NLAB + i], s);
    }
}

// Pass 3: hinge(||x - mean[label]|| - 0.1) for a 2-batch pair (L2-resident).
// float4 quartets: 8 lanes/point, 8 quartets staged (8 LDG.128 in flight),
// 3-deep shfl reduce, group-private hinge replicas.
__global__ void __launch_bounds__(THREADS) k_pass3(const float* __restrict__ emb,
                                                   const int* __restrict__ lab,
                                                   int b0) {
    __shared__ __align__(16) float s_mean[NLAB * DIM];
    __shared__ float s_h[NWARP * 4][NLAB];
    int tid = threadIdx.x, wid = tid >> 5, lane = tid & 31;
    int g = lane >> 3, s = lane & 7;

    int b = b0 + blockIdx.x / CHUNKS;
    int chunk = blockIdx.x % CHUNKS;

    for (int i = tid; i < NLAB * DIM; i += THREADS) {
        float c = g_counts[b * NLAB + i / DIM];
        s_mean[i] = g_sums[b * NLAB * DIM + i] / fmaxf(c, 1.f);
    }
    for (int i = tid; i < NWARP * 4 * NLAB; i += THREADS) (&s_h[0][0])[i] = 0.f;
    __syncthreads();

    const float4* e4 = (const float4*)(emb + ((size_t)b * NPTS + (size_t)chunk * CHUNK) * DIM);
    const int*    lbase = lab + (size_t)b * NPTS + (size_t)chunk * CHUNK;
    const float4* m4 = (const float4*)s_mean;
    float* wh = s_h[wid * 4 + g];
    int p0 = wid * WPTS;

    for (int w = 0; w < WPTS; w += 32) {
        int myl = lbase[p0 + w + lane];
        float4 v[8]; int lq[8];
        #pragma unroll
        for (int q = 0; q < 8; q++) {                  // 8 LDG.128 in flight
            int p = p0 + w + q * 4 + g;
            v[q] = e4[(size_t)p * 8 + s];              // 512B/warp contiguous
            lq[q] = __shfl_sync(0xffffffffu, myl, q * 4 + g);
        }
        #pragma unroll
        for (int q = 0; q < 8; q++) {
            float4 m = m4[lq[q] * 8 + s];
            float dx = v[q].x - m.x, dy = v[q].y - m.y;
            float dz = v[q].z - m.z, dw = v[q].w - m.w;
            float sq = dx * dx + dy * dy + dz * dz + dw * dw;
            sq += __shfl_xor_sync(0xffffffffu, sq, 1);
            sq += __shfl_xor_sync(0xffffffffu, sq, 2);
            sq += __shfl_xor_sync(0xffffffffu, sq, 4);
            if (s == 0) {
                float dist = sqrtf(sq + 1e-24f);
                wh[lq[q]] += fmaxf(dist - 0.1f, 0.f);  // group-private
            }
        }
    }
    __syncthreads();

    for (int i = tid; i < NLAB; i += THREADS) {
        float acc = 0.f;
        #pragma unroll
        for (int r = 0; r < NWARP * 4; r++) acc += s_h[r][i];
        atomicAdd(&g_hinge[b * NLAB + i], acc);
    }
}

// Finalize: ONE block, warp w handles batch w; warp 0 reduces at the end.
__global__ void __launch_bounds__(THREADS) k_final(float* __restrict__ out) {
    __shared__ float s_mn[BATCH][DIM][KINST + 1];  // +1 pad: conflict-free
    __shared__ float s_res[BATCH][2];
    int tid = threadIdx.x, b = tid >> 5, lane = tid & 31;

    // lane <-> label lane+1
    float cvec = g_counts[b * NLAB + 1 + lane];
    float pres = (cvec > 0.f) ? 1.f : 0.f;

    // batch all 32 sum-loads (lane = dim), one latency
    float mv[KINST];
    #pragma unroll
    for (int k = 0; k < KINST; k++)
        mv[k] = g_sums[b * NLAB * DIM + (k + 1) * DIM + lane];
    float hs = g_hinge[b * NLAB + 1 + lane];

    #pragma unroll
    for (int k = 0; k < KINST; k++) {
        float c = __shfl_sync(0xffffffffu, cvec, k);
        float m = mv[k] / fmaxf(c, 1.f);
        float nrm = m * m;
        #pragma unroll
        for (int o = 16; o; o >>= 1) nrm += __shfl_xor_sync(0xffffffffu, nrm, o);
        nrm = fmaxf(sqrtf(nrm), 1e-12f);
        s_mn[b][lane][k] = m / nrm;                 // lane = dim row
    }
    __syncwarp();

    // own column into registers (lane = instance j)
    float mc[DIM];
    #pragma unroll
    for (int d = 0; d < DIM; d++) mc[d] = s_mn[b][d][lane];

    float hp = 0.f, pm = 0.f;
    #pragma unroll 4
    for (int i = 0; i < KINST; i++) {
        float pi = __shfl_sync(0xffffffffu, pres, i);
        float mask = (lane > i) ? pi * pres : 0.f;
        float sq = 0.f;
        #pragma unroll
        for (int d = 0; d < DIM; d++) {
            float diff = s_mn[b][d][i] - mc[d];     // broadcast + register
            sq += diff * diff;
        }
        float dist = sqrtf(sq + 1e-24f);
        hp += fmaxf(1.0f - dist, 0.f) * mask;       // 2*DELTA_D = 1.0
        pm += mask;
    }

    float seg = hs / fmaxf(cvec, 1.f);
    float segsum = seg, ninst = pres;
    #pragma unroll
    for (int o = 16; o; o >>= 1) {
        segsum += __shfl_xor_sync(0xffffffffu, segsum, o);
        ninst  += __shfl_xor_sync(0xffffffffu, ninst, o);
        hp     += __shfl_xor_sync(0xffffffffu, hp, o);
        pm     += __shfl_xor_sync(0xffffffffu, pm, o);
    }
    if (lane == 0) {
        s_res[b][0] = segsum / (ninst + 1e-6f);
        s_res[b][1] = (ninst > 1.f) ? hp / (pm + 1e-6f) : 0.f;
    }
    __syncthreads();

    if (tid < 32) {
        float pull = (lane < BATCH) ? s_res[lane][0] : 0.f;
        float push = (lane < BATCH) ? s_res[lane][1] : 0.f;
        #pragma unroll
        for (int o = 4; o; o >>= 1) {
            pull += __shfl_xor_sync(0xffffffffu, pull, o);
            push += __shfl_xor_sync(0xffffffffu, push, o);
        }
        if (lane == 0) {
            pull *= (1.0f / BATCH);
            push *= (1.0f / BATCH);
            out[0] = pull + push;
            out[1] = pull;
            out[2] = push;
        }
    }
}

extern "C" void kernel_launch(void* const* d_in, const int* in_sizes, int n_in,
                              void* d_out, int out_size) {
    const float* emb = (const float*)d_in[0];
    const int*   lab = (const int*)d_in[1];
    float* out = (float*)d_out;
    (void)in_sizes; (void)n_in; (void)out_size;

    k_zero<<<(BATCH * NLAB * DIM + 255) / 256, 256>>>();
    // pairwise interleave: pass3(pair) runs while the pair is still L2-resident
    k_pass1<<<PAIRBLKS, THREADS>>>(emb, lab, 0);
    k_pass1<<<PAIRBLKS, THREADS>>>(emb, lab, 2);
    k_pass3<<<PAIRBLKS, THREADS>>>(emb, lab, 0);
    k_pass1<<<PAIRBLKS, THREADS>>>(emb, lab, 4);
    k_pass3<<<PAIRBLKS, THREADS>>>(emb, lab, 2);
    k_pass1<<<PAIRBLKS, THREADS>>>(emb, lab, 6);
    k_pass3<<<PAIRBLKS, THREADS>>>(emb, lab, 4);
    k_pass3<<<PAIRBLKS, THREADS>>>(emb, lab, 6);
    k_final<<<1, THREADS>>>(out);
}

// round 5
// speedup vs baseline: 1.1630x; 1.1630x over previous
#include <cuda_runtime.h>
#include <math.h>

#define BATCH  8
#define NPTS   131072
#define DIM    32
#define NLAB   33
#define KINST  32
#define CHUNK  256
#define CHUNKS (NPTS / CHUNK)        // 512 chunks per batch
#define THREADS 256
#define NWARP   8
#define WPTS    (CHUNK / NWARP)      // 32 points per warp per chunk
#define BPB     111                  // blocks per batch (888 = 148*6 total)
#define GRID    (BATCH * BPB)        // 888: one wave at 6 blocks/SM

// ---- scratch (no allocations allowed) ----
__device__ float g_sums[BATCH * NLAB * DIM];
__device__ float g_counts[BATCH * NLAB];
__device__ float g_hinge[BATCH * NLAB];

__global__ void k_zero() {
    int i = blockIdx.x * blockDim.x + threadIdx.x;
    if (i < BATCH * NLAB * DIM) g_sums[i] = 0.f;
    if (i < BATCH * NLAB) { g_counts[i] = 0.f; g_hinge[i] = 0.f; }
}

// Pass 1: per-(b,label) sums + counts. Persistent block pinned to one batch;
// SMEM accumulators zeroed/flushed ONCE per block. Warp-per-point lane-private
// RMW (race-free); 16 LDGs staged in flight.
__global__ void __launch_bounds__(THREADS, 6) k_pass1(const float* __restrict__ emb,
                                                      const int* __restrict__ lab) {
    __shared__ float s_sums[NWARP][NLAB * DIM];   // 33.8 KB
    __shared__ float s_cnt[NWARP][NLAB];
    int tid = threadIdx.x, wid = tid >> 5, lane = tid & 31;
    int b = blockIdx.x % BATCH;
    int c0 = blockIdx.x / BATCH;                  // 0..110

    for (int i = tid; i < NWARP * NLAB * DIM; i += THREADS) (&s_sums[0][0])[i] = 0.f;
    for (int i = tid; i < NWARP * NLAB; i += THREADS)       (&s_cnt[0][0])[i]  = 0.f;
    __syncthreads();

    float* ws = s_sums[wid];
    float* wc = s_cnt[wid];

    for (int chunk = c0; chunk < CHUNKS; chunk += BPB) {
        const float* ebase = emb + ((size_t)b * NPTS + (size_t)chunk * CHUNK) * DIM;
        const int*   lbase = lab + (size_t)b * NPTS + (size_t)chunk * CHUNK;
        int p0 = wid * WPTS;

        int myl = lbase[p0 + lane];                    // 32 labels, coalesced
        unsigned peers = __match_any_sync(0xffffffffu, myl);
        if ((__ffs(peers) - 1) == lane)                // one leader per label
            wc[myl] += (float)__popc(peers);           // distinct addrs: no race
        #pragma unroll
        for (int h = 0; h < 32; h += 16) {
            float v[16];
            #pragma unroll
            for (int i = 0; i < 16; i++)               // 16 LDGs in flight
                v[i] = ebase[(size_t)(p0 + h + i) * DIM + lane];
            #pragma unroll
            for (int i = 0; i < 16; i++) {
                int l = __shfl_sync(0xffffffffu, myl, h + i);
                ws[l * DIM + lane] += v[i];            // lane-private: no race
            }
        }
    }
    __syncthreads();

    for (int i = tid; i < NLAB * DIM; i += THREADS) {
        float s = 0.f;
        #pragma unroll
        for (int w = 0; w < NWARP; w++) s += s_sums[w][i];
        atomicAdd(&g_sums[b * NLAB * DIM + i], s);
    }
    for (int i = tid; i < NLAB; i += THREADS) {
        float s = 0.f;
        #pragma unroll
        for (int w = 0; w < NWARP; w++) s += s_cnt[w][i];
        atomicAdd(&g_counts[b * NLAB + i], s);
    }
}

// Pass 3: hinge(||x - mean[label]|| - 0.1). Persistent block per batch;
// means built once per block; hinge flushed once. float4 quartets
// (8 lanes/point), 8 LDG.128 staged, 3-deep shfl reduce, group-private
// hinge replicas (no races).
__global__ void __launch_bounds__(THREADS, 6) k_pass3(const float* __restrict__ emb,
                                                      const int* __restrict__ lab) {
    __shared__ __align__(16) float s_mean[NLAB * DIM];
    __shared__ float s_h[NWARP * 4][NLAB];
    int tid = threadIdx.x, wid = tid >> 5, lane = tid & 31;
    int g = lane >> 3, s = lane & 7;
    int b = blockIdx.x % BATCH;
    int c0 = blockIdx.x / BATCH;

    for (int i = tid; i < NLAB * DIM; i += THREADS) {
        float c = g_counts[b * NLAB + i / DIM];
        s_mean[i] = g_sums[b * NLAB * DIM + i] / fmaxf(c, 1.f);
    }
    for (int i = tid; i < NWARP * 4 * NLAB; i += THREADS) (&s_h[0][0])[i] = 0.f;
    __syncthreads();

    const float4* m4 = (const float4*)s_mean;
    float* wh = s_h[wid * 4 + g];

    for (int chunk = c0; chunk < CHUNKS; chunk += BPB) {
        const float4* e4 = (const float4*)(emb + ((size_t)b * NPTS + (size_t)chunk * CHUNK) * DIM);
        const int*    lbase = lab + (size_t)b * NPTS + (size_t)chunk * CHUNK;
        int p0 = wid * WPTS;

        int myl = lbase[p0 + lane];
        float4 v[8]; int lq[8];
        #pragma unroll
        for (int q = 0; q < 8; q++) {                  // 8 LDG.128 in flight
            int p = p0 + q * 4 + g;
            v[q] = e4[(size_t)p * 8 + s];              // 512B/warp contiguous
            lq[q] = __shfl_sync(0xffffffffu, myl, q * 4 + g);
        }
        #pragma unroll
        for (int q = 0; q < 8; q++) {
            float4 m = m4[lq[q] * 8 + s];
            float dx = v[q].x - m.x, dy = v[q].y - m.y;
            float dz = v[q].z - m.z, dw = v[q].w - m.w;
            float sq = dx * dx + dy * dy + dz * dz + dw * dw;
            sq += __shfl_xor_sync(0xffffffffu, sq, 1);
            sq += __shfl_xor_sync(0xffffffffu, sq, 2);
            sq += __shfl_xor_sync(0xffffffffu, sq, 4);
            if (s == 0) {
                float dist = sqrtf(sq + 1e-24f);
                wh[lq[q]] += fmaxf(dist - 0.1f, 0.f);  // group-private
            }
        }
    }
    __syncthreads();

    for (int i = tid; i < NLAB; i += THREADS) {
        float acc = 0.f;
        #pragma unroll
        for (int r = 0; r < NWARP * 4; r++) acc += s_h[r][i];
        atomicAdd(&g_hinge[b * NLAB + i], acc);
    }
}

// Finalize: ONE block, warp w handles batch w; warp 0 reduces at the end.
__global__ void __launch_bounds__(THREADS) k_final(float* __restrict__ out) {
    __shared__ float s_mn[BATCH][DIM][KINST + 1];
    __shared__ float s_res[BATCH][2];
    int tid = threadIdx.x, b = tid >> 5, lane = tid & 31;

    float cvec = g_counts[b * NLAB + 1 + lane];
    float pres = (cvec > 0.f) ? 1.f : 0.f;

    float mv[KINST];
    #pragma unroll
    for (int k = 0; k < KINST; k++)
        mv[k] = g_sums[b * NLAB * DIM + (k + 1) * DIM + lane];
    float hs = g_hinge[b * NLAB + 1 + lane];

    #pragma unroll
    for (int k = 0; k < KINST; k++) {
        float c = __shfl_sync(0xffffffffu, cvec, k);
        float m = mv[k] / fmaxf(c, 1.f);
        float nrm = m * m;
        #pragma unroll
        for (int o = 16; o; o >>= 1) nrm += __shfl_xor_sync(0xffffffffu, nrm, o);
        nrm = fmaxf(sqrtf(nrm), 1e-12f);
        s_mn[b][lane][k] = m / nrm;
    }
    __syncwarp();

    float mc[DIM];
    #pragma unroll
    for (int d = 0; d < DIM; d++) mc[d] = s_mn[b][d][lane];

    float hp = 0.f, pm = 0.f;
    #pragma unroll 4
    for (int i = 0; i < KINST; i++) {
        float pi = __shfl_sync(0xffffffffu, pres, i);
        float mask = (lane > i) ? pi * pres : 0.f;
        float sq = 0.f;
        #pragma unroll
        for (int d = 0; d < DIM; d++) {
            float diff = s_mn[b][d][i] - mc[d];
            sq += diff * diff;
        }
        float dist = sqrtf(sq + 1e-24f);
        hp += fmaxf(1.0f - dist, 0.f) * mask;       // 2*DELTA_D = 1.0
        pm += mask;
    }

    float seg = hs / fmaxf(cvec, 1.f);
    float segsum = seg, ninst = pres;
    #pragma unroll
    for (int o = 16; o; o >>= 1) {
        segsum += __shfl_xor_sync(0xffffffffu, segsum, o);
        ninst  += __shfl_xor_sync(0xffffffffu, ninst, o);
        hp     += __shfl_xor_sync(0xffffffffu, hp, o);
        pm     += __shfl_xor_sync(0xffffffffu, pm, o);
    }
    if (lane == 0) {
        s_res[b][0] = segsum / (ninst + 1e-6f);
        s_res[b][1] = (ninst > 1.f) ? hp / (pm + 1e-6f) : 0.f;
    }
    __syncthreads();

    if (tid < 32) {
        float pull = (lane < BATCH) ? s_res[lane][0] : 0.f;
        float push = (lane < BATCH) ? s_res[lane][1] : 0.f;
        #pragma unroll
        for (int o = 4; o; o >>= 1) {
            pull += __shfl_xor_sync(0xffffffffu, pull, o);
            push += __shfl_xor_sync(0xffffffffu, push, o);
        }
        if (lane == 0) {
            pull *= (1.0f / BATCH);
            push *= (1.0f / BATCH);
            out[0] = pull + push;
            out[1] = pull;
            out[2] = push;
        }
    }
}

extern "C" void kernel_launch(void* const* d_in, const int* in_sizes, int n_in,
                              void* d_out, int out_size) {
    const float* emb = (const float*)d_in[0];
    const int*   lab = (const int*)d_in[1];
    float* out = (float*)d_out;
    (void)in_sizes; (void)n_in; (void)out_size;

    k_zero<<<(BATCH * NLAB * DIM + 255) / 256, 256>>>();
    k_pass1<<<GRID, THREADS>>>(emb, lab);
    k_pass3<<<GRID, THREADS>>>(emb, lab);
    k_final<<<1, THREADS>>>(out);
}